// round 15
// baseline (speedup 1.0000x reference)
#include <cuda_runtime.h>
#include <cstdint>

typedef unsigned long long u64;

#define N_ACT 80
#define M_CON 85
#define NP1   81
#define PDHG_ITERS 200
#define POWER_ITERS 20

// ---- packed f32x2 helpers ----
static __device__ __forceinline__ u64 pk(float lo, float hi) {
    u64 r; asm("mov.b64 %0, {%1, %2};" : "=l"(r) : "f"(lo), "f"(hi)); return r;
}
static __device__ __forceinline__ float2 up(u64 v) {
    float2 f; asm("mov.b64 {%0, %1}, %2;" : "=f"(f.x), "=f"(f.y) : "l"(v)); return f;
}
static __device__ __forceinline__ u64 ff2(u64 a, u64 b, u64 c) {
    u64 r; asm("fma.rn.f32x2 %0, %1, %2, %3;" : "=l"(r) : "l"(a), "l"(b), "l"(c)); return r;
}
static __device__ __forceinline__ u64 add2(u64 a, u64 b) {
    u64 r; asm("add.rn.f32x2 %0, %1, %2;" : "=l"(r) : "l"(a), "l"(b)); return r;
}

__device__ __forceinline__ float warp_sum(float v) {
    #pragma unroll
    for (int off = 16; off > 0; off >>= 1)
        v += __shfl_xor_sync(0xffffffffu, v, off);
    return v;
}
__device__ __forceinline__ float warp_min(float v) {
    #pragma unroll
    for (int off = 16; off > 0; off >>= 1)
        v = fminf(v, __shfl_xor_sync(0xffffffffu, v, off));
    return v;
}
// combine partials across a 4-lane quad (lanes 4k..4k+3)
__device__ __forceinline__ float quad_sum(float v) {
    v += __shfl_xor_sync(0xffffffffu, v, 1);
    v += __shfl_xor_sync(0xffffffffu, v, 2);
    return v;
}

// 24-float packed dot: G[12] (u64 pairs) . V-quarter (6 ulonglong2 = 24 floats)
__device__ __forceinline__ float dot24(const u64* __restrict__ G,
                                       const ulonglong2* __restrict__ v2) {
    u64 a0 = 0, a1 = 0, a2 = 0, a3 = 0;
    ulonglong2 p0 = v2[0], p1 = v2[1], p2 = v2[2];
    a0 = ff2(G[0], p0.x, a0);  a1 = ff2(G[1], p0.y, a1);
    a2 = ff2(G[2], p1.x, a2);  a3 = ff2(G[3], p1.y, a3);
    a0 = ff2(G[4], p2.x, a0);  a1 = ff2(G[5], p2.y, a1);
    ulonglong2 p3 = v2[3], p4 = v2[4], p5 = v2[5];
    a2 = ff2(G[6], p3.x, a2);  a3 = ff2(G[7], p3.y, a3);
    a0 = ff2(G[8], p4.x, a0);  a1 = ff2(G[9], p4.y, a1);
    a2 = ff2(G[10], p5.x, a2); a3 = ff2(G[11], p5.y, a3);
    u64 s = add2(add2(a0, a1), add2(a2, a3));
    float2 f = up(s);
    return f.x + f.y;
}

__global__ __launch_bounds__(384, 2)
void acp_kernel(const float* __restrict__ xhat,
                const float* __restrict__ Aglob,
                const float* __restrict__ bglob,
                float* __restrict__ out)
{
    // Vectors padded to 96 floats (4 quarters x 24); pads are hard zeros.
    __shared__ __align__(16) float sh_vec[96];   // v / z_bar (0..80)
    __shared__ __align__(16) float sh_y[96];     // Gv / y    (0..84)
    __shared__ __align__(16) float sh_x0[96];    // x0        (0..79)
    __shared__ __align__(16) float sh_dv[96];    // x_hat-x0  (0..79)
    __shared__ __align__(16) float sh_d[96];     // row norms (0..84)
    __shared__ float sh_red[12];
    __shared__ float As[M_CON * 81];             // pitch 81

    const int t    = threadIdx.x;        // 0..383
    const int lane = t & 31;
    const int wid  = t >> 5;             // 0..11
    const int part = lane & 3;           // quarter 0..3 within quad
    const int idx  = (lane >> 2) * 12 + wid;  // 0..95, interleaved over warps
    const bool rowAct = (idx < M_CON);
    const bool colAct = (idx < NP1);
    const int prob = blockIdx.x;

    // ---- stage A into shared (coalesced) ----
    {
        const float* Ap = Aglob + (size_t)prob * (M_CON * N_ACT);
        for (int i = t; i < M_CON * N_ACT; i += 384) {
            int rr = i / N_ACT;
            int cc = i - rr * N_ACT;
            As[rr * 81 + cc] = Ap[i];
        }
    }
    if (t < 96) {
        sh_y[t]  = 0.0f;
        sh_vec[t] = (t < NP1) ? 1.0f : 0.0f;   // power-iter v0 = ones
        sh_x0[t] = 0.0f;
        sh_dv[t] = 0.0f;
        sh_d[t]  = 0.0f;
    }
    if (t >= 96 && t < 108) sh_red[t - 96] = 0.0f;
    __syncthreads();

    // ---- per-thread packed quarters ----
    // Row: quarter p covers logical [24p..24p+23] of rowG (0..79 = A, 80 = d).
    // Col: quarter p covers logical [24p..24p+23] of column (0..84; 84 = A[84][idx]).
    u64 RP[12], CP[12];
    float bval = 0.0f;
    #pragma unroll
    for (int k = 0; k < 12; k++) { RP[k] = 0; CP[k] = 0; }

    // row fill + norm (quad-reduced)
    {
        float ss = 0.0f;
        if (rowAct) {
            const float* Ar = &As[idx * 81];
            if (part < 3) {
                #pragma unroll
                for (int k = 0; k < 12; k++) {
                    float lo = Ar[24 * part + 2*k], hi = Ar[24 * part + 2*k + 1];
                    RP[k] = pk(lo, hi);
                    ss = fmaf(lo, lo, fmaf(hi, hi, ss));
                }
            } else {
                #pragma unroll
                for (int k = 0; k < 4; k++) {     // j = 72..79
                    float lo = Ar[72 + 2*k], hi = Ar[73 + 2*k];
                    RP[k] = pk(lo, hi);
                    ss = fmaf(lo, lo, fmaf(hi, hi, ss));
                }
            }
        }
        float tot = quad_sum(ss);
        if (rowAct) {
            float dval = fmaxf(sqrtf(tot), 1e-12f);
            if (part == 3) RP[4] = pk(dval, 0.0f);   // logical 80 = d_r
            if (part == 0) sh_d[idx] = dval;
            bval = bglob[(size_t)prob * M_CON + idx];
        }
    }
    __syncthreads();                     // sh_d complete (pads still zero)

    // col fill
    if (colAct) {
        if (idx < N_ACT) {
            if (part < 3) {
                #pragma unroll
                for (int k = 0; k < 12; k++) {
                    int j = 24 * part + 2*k;
                    CP[k] = pk(As[j * 81 + idx], As[(j + 1) * 81 + idx]);
                }
            } else {
                #pragma unroll
                for (int k = 0; k < 6; k++) {     // j = 72..83
                    int j = 72 + 2*k;
                    CP[k] = pk(As[j * 81 + idx], As[(j + 1) * 81 + idx]);
                }
                CP[6] = pk(As[84 * 81 + idx], 0.0f);  // logical 84
            }
        } else {   // idx == 80: column is d (sh_d zero-padded to 96)
            #pragma unroll
            for (int k = 0; k < 12; k++)
                CP[k] = pk(sh_d[24 * part + 2*k], sh_d[24 * part + 2*k + 1]);
        }
    }

    const ulonglong2* vecQ = reinterpret_cast<const ulonglong2*>(sh_vec) + 6 * part;
    const ulonglong2* yQ   = reinterpret_cast<const ulonglong2*>(sh_y)   + 6 * part;

    #define RED12(R) (((R[0]+R[1])+(R[2]+R[3])) + ((R[4]+R[5])+(R[6]+R[7])) + \
                      ((R[8]+R[9])+(R[10]+R[11])))

    // ---- power iteration: v <- GT(G v), normalize every 3rd iter + last ----
    for (int pi = 0; pi < POWER_ITERS; pi++) {
        float pr = dot24(RP, vecQ);                 // zero for inactive threads
        float g  = quad_sum(pr);
        if (rowAct && part == 0) sh_y[idx] = g;
        __syncthreads();
        float pc = dot24(CP, yQ);
        float w  = quad_sum(pc);
        const bool norm_now = ((pi % 3) == 2) || (pi == POWER_ITERS - 1);
        if (norm_now) {
            float ss = warp_sum((colAct && part == 0) ? w * w : 0.0f);
            if (lane == 0) sh_red[wid] = ss;
            __syncthreads();
            float nrm = sqrtf(RED12(sh_red)) + 1e-12f;
            if (colAct && part == 0) sh_vec[idx] = w / nrm;
        } else {
            if (colAct && part == 0) sh_vec[idx] = w;
        }
        __syncthreads();
    }
    // L = ||G v||
    {
        float pr = dot24(RP, vecQ);
        float g  = quad_sum(pr);
        float ss = warp_sum((rowAct && part == 0) ? g * g : 0.0f);
        if (lane == 0) sh_red[wid] = ss;
        __syncthreads();
    }
    const float Lnrm = sqrtf(RED12(sh_red));
    const float tau  = 0.9f / fmaxf(Lnrm, 1e-6f);   // sigma == tau

    // ---- PDHG: 200 fixed iterations ----
    if (t < 96) sh_y[t] = 0.0f;
    float zv = 0.0f, yv = 0.0f;
    const float cterm = (idx == N_ACT) ? -1.0f : 0.0f;
    __syncthreads();

    for (int it = 0; it < PDHG_ITERS; it++) {
        float pc  = dot24(CP, yQ);
        float gty = quad_sum(pc);
        float znew = fmaxf(zv - tau * (cterm + gty), 0.0f);
        if (colAct && part == 0) sh_vec[idx] = 2.0f * znew - zv;   // z_bar
        zv = znew;
        __syncthreads();
        float pr = dot24(RP, vecQ);
        float gz = quad_sum(pr);
        yv = fmaxf(yv + tau * (gz - bval), 0.0f);
        if (rowAct && part == 0) sh_y[idx] = yv;
        __syncthreads();
    }

    // ---- alpha map ----
    if (idx < N_ACT && part == 0) {
        sh_x0[idx] = zv;
        sh_dv[idx] = xhat[(size_t)prob * N_ACT + idx] - zv;
    }
    __syncthreads();

    const float INF = __int_as_float(0x7f800000);
    float ai;
    {
        // x0/dv pads (incl. logical 80) are zero -> RP's dval term vanishes.
        const ulonglong2* x0Q = reinterpret_cast<const ulonglong2*>(sh_x0) + 6 * part;
        const ulonglong2* dvQ = reinterpret_cast<const ulonglong2*>(sh_dv) + 6 * part;
        float p0 = dot24(RP, x0Q);
        float p1 = dot24(RP, dvQ);
        float ax0 = quad_sum(p0);
        float ad  = quad_sum(p1);
        if (rowAct) {
            float slack = fmaxf(bval - ax0, 0.0f);
            ai = (ad > 0.0f) ? (slack / (ad + 1e-12f)) : INF;
        } else {
            ai = INF;
        }
    }
    ai = warp_min(ai);
    if (lane == 0) sh_red[wid] = ai;
    __syncthreads();
    float alpha = fminf(fminf(fminf(sh_red[0], sh_red[1]), fminf(sh_red[2], sh_red[3])),
                  fminf(fminf(fminf(sh_red[4], sh_red[5]), fminf(sh_red[6], sh_red[7])),
                        fminf(fminf(sh_red[8], sh_red[9]), fminf(sh_red[10], sh_red[11]))));
    if (!isfinite(alpha)) alpha = 1.0f;
    alpha = fminf(fmaxf(alpha - 1e-9f, 0.0f), 1.0f);

    if (idx < N_ACT && part == 0)
        out[(size_t)prob * N_ACT + idx] = fmaxf(sh_x0[idx] + alpha * sh_dv[idx], 0.0f);

    #undef RED12
}

extern "C" void kernel_launch(void* const* d_in, const int* in_sizes, int n_in,
                              void* d_out, int out_size)
{
    const float* xhat = (const float*)d_in[0];
    const float* A    = (const float*)d_in[1];
    const float* b    = (const float*)d_in[2];
    float* out        = (float*)d_out;
    int P = in_sizes[0] / N_ACT;     // 1024 problems
    acp_kernel<<<P, 384>>>(xhat, A, b, out);
}

// round 16
// speedup vs baseline: 1.6022x; 1.6022x over previous
#include <cuda_runtime.h>
#include <cstdint>

typedef unsigned long long u64;

#define N_ACT 80
#define M_CON 85
#define NP1   81
#define PDHG_ITERS 200
#define POWER_ITERS 20

// ---- packed f32x2 helpers ----
static __device__ __forceinline__ u64 pk(float lo, float hi) {
    u64 r; asm("mov.b64 %0, {%1, %2};" : "=l"(r) : "f"(lo), "f"(hi)); return r;
}
static __device__ __forceinline__ float2 up(u64 v) {
    float2 f; asm("mov.b64 {%0, %1}, %2;" : "=f"(f.x), "=f"(f.y) : "l"(v)); return f;
}
static __device__ __forceinline__ u64 ff2(u64 a, u64 b, u64 c) {
    u64 r; asm("fma.rn.f32x2 %0, %1, %2, %3;" : "=l"(r) : "l"(a), "l"(b), "l"(c)); return r;
}
static __device__ __forceinline__ u64 add2(u64 a, u64 b) {
    u64 r; asm("add.rn.f32x2 %0, %1, %2;" : "=l"(r) : "l"(a), "l"(b)); return r;
}

__device__ __forceinline__ float warp_sum(float v) {
    #pragma unroll
    for (int off = 16; off > 0; off >>= 1)
        v += __shfl_xor_sync(0xffffffffu, v, off);
    return v;
}
__device__ __forceinline__ float warp_min(float v) {
    #pragma unroll
    for (int off = 16; off > 0; off >>= 1)
        v = fminf(v, __shfl_xor_sync(0xffffffffu, v, off));
    return v;
}

// 44-float packed dot: G[22] (u64 pairs) . V-half (11 ulonglong2 = 44 floats)
__device__ __forceinline__ float dot44(const u64* __restrict__ G,
                                       const ulonglong2* __restrict__ v2) {
    u64 a0 = 0, a1 = 0, a2 = 0, a3 = 0;
    #pragma unroll
    for (int q = 0; q < 10; q += 2) {
        ulonglong2 pa = v2[q];
        ulonglong2 pb = v2[q + 1];
        a0 = ff2(G[2*q + 0], pa.x, a0);
        a1 = ff2(G[2*q + 1], pa.y, a1);
        a2 = ff2(G[2*q + 2], pb.x, a2);
        a3 = ff2(G[2*q + 3], pb.y, a3);
    }
    ulonglong2 pt = v2[10];
    a0 = ff2(G[20], pt.x, a0);
    a1 = ff2(G[21], pt.y, a1);
    u64 s = add2(add2(a0, a1), add2(a2, a3));
    float2 f = up(s);
    return f.x + f.y;
}

__global__ __launch_bounds__(256, 2)
void acp_kernel(const float* __restrict__ xhat,
                const float* __restrict__ Aglob,
                const float* __restrict__ bglob,
                float* __restrict__ out)
{
    // All vectors padded to 88 floats (22 ulonglong2); pads are hard zeros.
    __shared__ __align__(16) float sh_vec[88];   // v / z_bar (0..80)
    __shared__ __align__(16) float sh_y[88];     // Gv / y    (0..84)
    __shared__ __align__(16) float sh_x0[88];    // x0        (0..79)
    __shared__ __align__(16) float sh_dv[88];    // x_hat-x0  (0..79)
    __shared__ __align__(16) float sh_d[88];     // row norms (0..84)
    __shared__ float sh_red[8];
    __shared__ float As[M_CON * 81];             // pitch 81

    const int t    = threadIdx.x;        // 0..255
    const int lane = t & 31;
    const int wid  = t >> 5;             // 0..7
    const int part = lane & 1;           // pair = lanes (2k, 2k+1)
    const int idx  = (lane >> 1) * 8 + wid;   // 0..127, interleaved over warps
    const bool rowAct = (idx < M_CON);
    const bool colAct = (idx < NP1);
    const int prob = blockIdx.x;

    // ---- stage A into shared (coalesced) ----
    {
        const float* Ap = Aglob + (size_t)prob * (M_CON * N_ACT);
        for (int i = t; i < M_CON * N_ACT; i += 256) {
            int rr = i / N_ACT;
            int cc = i - rr * N_ACT;
            As[rr * 81 + cc] = Ap[i];
        }
    }
    if (t < 88) {
        sh_y[t]  = 0.0f;
        sh_vec[t] = (t < NP1) ? 1.0f : 0.0f;   // power-iter v0 = ones
        sh_x0[t] = 0.0f;
        sh_dv[t] = 0.0f;
        sh_d[t]  = 0.0f;
    }
    __syncthreads();

    // ---- per-thread packed halves ----
    u64 RP[22];        // row half: part0 = A[idx][0..43]; part1 = A[idx][44..79], slot80=d
    u64 CP[22];        // col half: part p = G[44p .. 44p+43][idx] (zeros past 84)
    float bval = 0.0f;

    #pragma unroll
    for (int k = 0; k < 22; k++) { RP[k] = 0; CP[k] = 0; }

    // row fill + norm (shfl hoisted to warp scope)
    {
        float ss = 0.0f;
        if (rowAct) {
            const float* Ar = &As[idx * 81];
            if (part == 0) {
                #pragma unroll
                for (int k = 0; k < 22; k++) {
                    float lo = Ar[2*k], hi = Ar[2*k + 1];
                    RP[k] = pk(lo, hi);
                    ss = fmaf(lo, lo, fmaf(hi, hi, ss));
                }
            } else {
                #pragma unroll
                for (int k = 0; k < 18; k++) {
                    float lo = Ar[44 + 2*k], hi = Ar[45 + 2*k];
                    RP[k] = pk(lo, hi);
                    ss = fmaf(lo, lo, fmaf(hi, hi, ss));
                }
            }
        }
        float tot = ss + __shfl_xor_sync(0xffffffffu, ss, 1);
        if (rowAct) {
            float dval = fmaxf(sqrtf(tot), 1e-12f);
            if (part == 1) RP[18] = pk(dval, 0.0f);   // element 80 of row-G
            if (part == 0) sh_d[idx] = dval;
            bval = bglob[(size_t)prob * M_CON + idx];
        }
    }
    __syncthreads();                   // sh_d ready (pads still zero)

    // col fill
    if (colAct) {
        if (idx < N_ACT) {
            if (part == 0) {
                #pragma unroll
                for (int k = 0; k < 22; k++)
                    CP[k] = pk(As[(2*k) * 81 + idx], As[(2*k + 1) * 81 + idx]);
            } else {
                #pragma unroll
                for (int k = 0; k < 20; k++)
                    CP[k] = pk(As[(44 + 2*k) * 81 + idx], As[(45 + 2*k) * 81 + idx]);
                CP[20] = pk(As[84 * 81 + idx], 0.0f);  // j = 84 (+ zero)
            }
        } else {   // idx == 80: column is d (sh_d zero-padded to 88)
            #pragma unroll
            for (int k = 0; k < 22; k++)
                CP[k] = pk(sh_d[44 * part + 2*k], sh_d[44 * part + 2*k + 1]);
        }
    }

    const ulonglong2* vecV = reinterpret_cast<const ulonglong2*>(sh_vec) + 11 * part;
    const ulonglong2* yV   = reinterpret_cast<const ulonglong2*>(sh_y)   + 11 * part;

    // ---- power iteration: v <- GT(G v), normalize every 3rd iter + last ----
    for (int pi = 0; pi < POWER_ITERS; pi++) {
        float pr = dot44(RP, vecV);                     // zero for inactive
        float g  = pr + __shfl_xor_sync(0xffffffffu, pr, 1);
        if (rowAct && part == 0) sh_y[idx] = g;
        __syncthreads();
        float pc = dot44(CP, yV);
        float w  = pc + __shfl_xor_sync(0xffffffffu, pc, 1);
        const bool norm_now = ((pi % 3) == 2) || (pi == POWER_ITERS - 1);
        if (norm_now) {
            float ss = warp_sum((colAct && part == 0) ? w * w : 0.0f);
            if (lane == 0) sh_red[wid] = ss;
            __syncthreads();
            float nrm = sqrtf(((sh_red[0] + sh_red[1]) + (sh_red[2] + sh_red[3])) +
                              ((sh_red[4] + sh_red[5]) + (sh_red[6] + sh_red[7]))) + 1e-12f;
            if (colAct && part == 0) sh_vec[idx] = w / nrm;
        } else {
            if (colAct && part == 0) sh_vec[idx] = w;
        }
        __syncthreads();
    }
    // L = ||G v||
    {
        float pr = dot44(RP, vecV);
        float g  = pr + __shfl_xor_sync(0xffffffffu, pr, 1);
        float ss = warp_sum((rowAct && part == 0) ? g * g : 0.0f);
        if (lane == 0) sh_red[wid] = ss;
        __syncthreads();
    }
    const float Lnrm = sqrtf(((sh_red[0] + sh_red[1]) + (sh_red[2] + sh_red[3])) +
                             ((sh_red[4] + sh_red[5]) + (sh_red[6] + sh_red[7])));
    const float tau  = 0.9f / fmaxf(Lnrm, 1e-6f);       // sigma == tau

    // ---- PDHG: 200 fixed iterations, unrolled x2 (halved loop overhead) ----
    if (t < 88) sh_y[t] = 0.0f;
    float zv = 0.0f, yv = 0.0f;
    const float cterm = (idx == N_ACT) ? -1.0f : 0.0f;
    const float ntau  = -tau;
    __syncthreads();

    #define PDHG_HALF_ITER()                                                \
    {                                                                       \
        float pc  = dot44(CP, yV);                                          \
        float gty = pc + __shfl_xor_sync(0xffffffffu, pc, 1);               \
        float znew = fmaxf(fmaf(ntau, cterm + gty, zv), 0.0f);              \
        if (colAct && part == 0) sh_vec[idx] = 2.0f * znew - zv;            \
        zv = znew;                                                          \
        __syncthreads();                                                    \
        float pr = dot44(RP, vecV);                                         \
        float gz = pr + __shfl_xor_sync(0xffffffffu, pr, 1);                \
        yv = fmaxf(fmaf(tau, gz - bval, yv), 0.0f);                         \
        if (rowAct && part == 0) sh_y[idx] = yv;                            \
        __syncthreads();                                                    \
    }

    for (int it = 0; it < PDHG_ITERS / 2; it++) {
        PDHG_HALF_ITER();
        PDHG_HALF_ITER();
    }
    #undef PDHG_HALF_ITER

    // ---- alpha map ----
    if (idx < N_ACT && part == 0) {
        sh_x0[idx] = zv;
        sh_dv[idx] = xhat[(size_t)prob * N_ACT + idx] - zv;
    }
    __syncthreads();

    const float INF = __int_as_float(0x7f800000);
    float ai;
    {
        // sh_x0/sh_dv pads (incl. slot 80) are zero -> RP's dval term vanishes.
        const ulonglong2* x0V = reinterpret_cast<const ulonglong2*>(sh_x0) + 11 * part;
        const ulonglong2* dvV = reinterpret_cast<const ulonglong2*>(sh_dv) + 11 * part;
        float p0 = dot44(RP, x0V);
        float p1 = dot44(RP, dvV);
        float ax0 = p0 + __shfl_xor_sync(0xffffffffu, p0, 1);
        float ad  = p1 + __shfl_xor_sync(0xffffffffu, p1, 1);
        if (rowAct) {
            float slack = fmaxf(bval - ax0, 0.0f);
            ai = (ad > 0.0f) ? (slack / (ad + 1e-12f)) : INF;
        } else {
            ai = INF;
        }
    }
    ai = warp_min(ai);
    if (lane == 0) sh_red[wid] = ai;
    __syncthreads();
    float alpha = fminf(fminf(fminf(sh_red[0], sh_red[1]), fminf(sh_red[2], sh_red[3])),
                        fminf(fminf(sh_red[4], sh_red[5]), fminf(sh_red[6], sh_red[7])));
    if (!isfinite(alpha)) alpha = 1.0f;
    alpha = fminf(fmaxf(alpha - 1e-9f, 0.0f), 1.0f);

    if (idx < N_ACT && part == 0)
        out[(size_t)prob * N_ACT + idx] = fmaxf(sh_x0[idx] + alpha * sh_dv[idx], 0.0f);
}

extern "C" void kernel_launch(void* const* d_in, const int* in_sizes, int n_in,
                              void* d_out, int out_size)
{
    const float* xhat = (const float*)d_in[0];
    const float* A    = (const float*)d_in[1];
    const float* b    = (const float*)d_in[2];
    float* out        = (float*)d_out;
    int P = in_sizes[0] / N_ACT;     // 1024 problems
    acp_kernel<<<P, 256>>>(xhat, A, b, out);
}

// round 17
// speedup vs baseline: 1.6104x; 1.0051x over previous
#include <cuda_runtime.h>
#include <cstdint>

typedef unsigned long long u64;

#define N_ACT 80
#define M_CON 85
#define NP1   81
#define PDHG_ITERS 200
#define POWER_ITERS 20

// ---- packed f32x2 helpers ----
static __device__ __forceinline__ u64 pk(float lo, float hi) {
    u64 r; asm("mov.b64 %0, {%1, %2};" : "=l"(r) : "f"(lo), "f"(hi)); return r;
}
static __device__ __forceinline__ float2 up(u64 v) {
    float2 f; asm("mov.b64 {%0, %1}, %2;" : "=f"(f.x), "=f"(f.y) : "l"(v)); return f;
}
static __device__ __forceinline__ u64 ff2(u64 a, u64 b, u64 c) {
    u64 r; asm("fma.rn.f32x2 %0, %1, %2, %3;" : "=l"(r) : "l"(a), "l"(b), "l"(c)); return r;
}
static __device__ __forceinline__ u64 add2(u64 a, u64 b) {
    u64 r; asm("add.rn.f32x2 %0, %1, %2;" : "=l"(r) : "l"(a), "l"(b)); return r;
}

__device__ __forceinline__ float warp_sum(float v) {
    #pragma unroll
    for (int off = 16; off > 0; off >>= 1)
        v += __shfl_xor_sync(0xffffffffu, v, off);
    return v;
}
__device__ __forceinline__ float warp_min(float v) {
    #pragma unroll
    for (int off = 16; off > 0; off >>= 1)
        v = fminf(v, __shfl_xor_sync(0xffffffffu, v, off));
    return v;
}

// 44-float packed dot: G[22] (u64 pairs) . V-half (11 ulonglong2 = 44 floats)
__device__ __forceinline__ float dot44(const u64* __restrict__ G,
                                       const ulonglong2* __restrict__ v2) {
    u64 a0 = 0, a1 = 0, a2 = 0, a3 = 0;
    #pragma unroll
    for (int q = 0; q < 10; q += 2) {
        ulonglong2 pa = v2[q];
        ulonglong2 pb = v2[q + 1];
        a0 = ff2(G[2*q + 0], pa.x, a0);
        a1 = ff2(G[2*q + 1], pa.y, a1);
        a2 = ff2(G[2*q + 2], pb.x, a2);
        a3 = ff2(G[2*q + 3], pb.y, a3);
    }
    ulonglong2 pt = v2[10];
    a0 = ff2(G[20], pt.x, a0);
    a1 = ff2(G[21], pt.y, a1);
    u64 s = add2(add2(a0, a1), add2(a2, a3));
    float2 f = up(s);
    return f.x + f.y;
}

__global__ __launch_bounds__(256, 2)
void acp_kernel(const float* __restrict__ xhat,
                const float* __restrict__ Aglob,
                const float* __restrict__ bglob,
                float* __restrict__ out)
{
    // All vectors padded to 88 floats (22 ulonglong2); pads are hard zeros.
    __shared__ __align__(16) float sh_vec[88];   // v / z_bar (0..80)
    __shared__ __align__(16) float sh_y[88];     // Gv / y    (0..84)
    __shared__ __align__(16) float sh_x0[88];    // x0        (0..79)
    __shared__ __align__(16) float sh_dv[88];    // x_hat-x0  (0..79)
    __shared__ __align__(16) float sh_d[88];     // row norms (0..84)
    __shared__ float sh_red[8];
    __shared__ float As[M_CON * 81];             // pitch 81

    const int t    = threadIdx.x;        // 0..255
    const int lane = t & 31;
    const int wid  = t >> 5;             // 0..7
    const int part = lane & 1;           // pair = lanes (2k, 2k+1)
    const int idx  = (lane >> 1) * 8 + wid;   // 0..127, interleaved over warps
    const bool rowAct = (idx < M_CON);
    const bool colAct = (idx < NP1);
    const int prob = blockIdx.x;

    // ---- stage A into shared (coalesced) ----
    {
        const float* Ap = Aglob + (size_t)prob * (M_CON * N_ACT);
        for (int i = t; i < M_CON * N_ACT; i += 256) {
            int rr = i / N_ACT;
            int cc = i - rr * N_ACT;
            As[rr * 81 + cc] = Ap[i];
        }
    }
    if (t < 88) {
        sh_y[t]  = 0.0f;
        sh_vec[t] = (t < NP1) ? 1.0f : 0.0f;   // power-iter v0 = ones
        sh_x0[t] = 0.0f;
        sh_dv[t] = 0.0f;
        sh_d[t]  = 0.0f;
    }
    __syncthreads();

    // ---- per-thread packed halves ----
    u64 RP[22];        // row half: part0 = A[idx][0..43]; part1 = A[idx][44..79], slot80=d
    u64 CP[22];        // col half: part p = G[44p .. 44p+43][idx] (zeros past 84)
    float bval = 0.0f;

    #pragma unroll
    for (int k = 0; k < 22; k++) { RP[k] = 0; CP[k] = 0; }

    // row fill + norm (shfl hoisted to warp scope)
    {
        float ss = 0.0f;
        if (rowAct) {
            const float* Ar = &As[idx * 81];
            if (part == 0) {
                #pragma unroll
                for (int k = 0; k < 22; k++) {
                    float lo = Ar[2*k], hi = Ar[2*k + 1];
                    RP[k] = pk(lo, hi);
                    ss = fmaf(lo, lo, fmaf(hi, hi, ss));
                }
            } else {
                #pragma unroll
                for (int k = 0; k < 18; k++) {
                    float lo = Ar[44 + 2*k], hi = Ar[45 + 2*k];
                    RP[k] = pk(lo, hi);
                    ss = fmaf(lo, lo, fmaf(hi, hi, ss));
                }
            }
        }
        float tot = ss + __shfl_xor_sync(0xffffffffu, ss, 1);
        if (rowAct) {
            float dval = fmaxf(sqrtf(tot), 1e-12f);
            if (part == 1) RP[18] = pk(dval, 0.0f);   // element 80 of row-G
            if (part == 0) sh_d[idx] = dval;
            bval = bglob[(size_t)prob * M_CON + idx];
        }
    }
    __syncthreads();                   // sh_d ready (pads still zero)

    // col fill
    if (colAct) {
        if (idx < N_ACT) {
            if (part == 0) {
                #pragma unroll
                for (int k = 0; k < 22; k++)
                    CP[k] = pk(As[(2*k) * 81 + idx], As[(2*k + 1) * 81 + idx]);
            } else {
                #pragma unroll
                for (int k = 0; k < 20; k++)
                    CP[k] = pk(As[(44 + 2*k) * 81 + idx], As[(45 + 2*k) * 81 + idx]);
                CP[20] = pk(As[84 * 81 + idx], 0.0f);  // j = 84 (+ zero)
            }
        } else {   // idx == 80: column is d (sh_d zero-padded to 88)
            #pragma unroll
            for (int k = 0; k < 22; k++)
                CP[k] = pk(sh_d[44 * part + 2*k], sh_d[44 * part + 2*k + 1]);
        }
    }

    const ulonglong2* vecV = reinterpret_cast<const ulonglong2*>(sh_vec) + 11 * part;
    const ulonglong2* yV   = reinterpret_cast<const ulonglong2*>(sh_y)   + 11 * part;

    // ---- power iteration: v <- GT(G v), normalize every 4th iter + last ----
    // Overflow bound: ||G||2 <= sqrt(||G||1*||G||inf) ~ 97 -> 4 unnormalized
    // GT(G .) steps grow sum(w^2) <= (L^2)^8 ~ 6e31 << FLT_MAX. Safe.
    for (int pi = 0; pi < POWER_ITERS; pi++) {
        float pr = dot44(RP, vecV);                     // zero for inactive
        float g  = pr + __shfl_xor_sync(0xffffffffu, pr, 1);
        if (rowAct && part == 0) sh_y[idx] = g;
        __syncthreads();
        float pc = dot44(CP, yV);
        float w  = pc + __shfl_xor_sync(0xffffffffu, pc, 1);
        const bool norm_now = ((pi & 3) == 3) || (pi == POWER_ITERS - 1);
        if (norm_now) {
            float ss = warp_sum((colAct && part == 0) ? w * w : 0.0f);
            if (lane == 0) sh_red[wid] = ss;
            __syncthreads();
            float nrm = sqrtf(((sh_red[0] + sh_red[1]) + (sh_red[2] + sh_red[3])) +
                              ((sh_red[4] + sh_red[5]) + (sh_red[6] + sh_red[7]))) + 1e-12f;
            if (colAct && part == 0) sh_vec[idx] = w / nrm;
        } else {
            if (colAct && part == 0) sh_vec[idx] = w;
        }
        __syncthreads();
    }
    // L = ||G v||  (sh_y re-zero folded into this phase: its last read was
    // before the preceding barrier, so zeroing here is race-free)
    {
        float pr = dot44(RP, vecV);
        float g  = pr + __shfl_xor_sync(0xffffffffu, pr, 1);
        if (t < 88) sh_y[t] = 0.0f;       // y = 0 for PDHG
        float ss = warp_sum((rowAct && part == 0) ? g * g : 0.0f);
        if (lane == 0) sh_red[wid] = ss;
        __syncthreads();
    }
    const float Lnrm = sqrtf(((sh_red[0] + sh_red[1]) + (sh_red[2] + sh_red[3])) +
                             ((sh_red[4] + sh_red[5]) + (sh_red[6] + sh_red[7])));
    const float tau  = 0.9f / fmaxf(Lnrm, 1e-6f);       // sigma == tau
    const float ntau = -tau;

    // ---- PDHG: 200 fixed iterations, unrolled x2 ----
    // tau*cterm hoisted: znew = relu((zv - tau*cterm) - tau*gty); carried state
    // zv0 = zv - tau*cterm, so zv = zv0 + tc with tc = tau*cterm.
    // For idx != 80: tc = 0 (identical); for idx == 80: cterm = -1 -> tc = tau.
    const float tc = (idx == N_ACT) ? tau : 0.0f;
    float zv = 0.0f, yv = 0.0f;
    // (no barrier needed: sh_y zero + sh_vec final both precede last barrier)

    #define PDHG_HALF_ITER()                                                \
    {                                                                       \
        float pc  = dot44(CP, yV);                                          \
        float gty = pc + __shfl_xor_sync(0xffffffffu, pc, 1);               \
        float znew = fmaxf(fmaf(ntau, gty, zv + tc), 0.0f);                 \
        if (colAct && part == 0) sh_vec[idx] = 2.0f * znew - zv;            \
        zv = znew;                                                          \
        __syncthreads();                                                    \
        float pr = dot44(RP, vecV);                                         \
        float gz = pr + __shfl_xor_sync(0xffffffffu, pr, 1);                \
        yv = fmaxf(fmaf(tau, gz - bval, yv), 0.0f);                         \
        if (rowAct && part == 0) sh_y[idx] = yv;                            \
        __syncthreads();                                                    \
    }

    for (int it = 0; it < PDHG_ITERS / 2; it++) {
        PDHG_HALF_ITER();
        PDHG_HALF_ITER();
    }
    #undef PDHG_HALF_ITER

    // ---- alpha map ----
    if (idx < N_ACT && part == 0) {
        sh_x0[idx] = zv;
        sh_dv[idx] = xhat[(size_t)prob * N_ACT + idx] - zv;
    }
    __syncthreads();

    const float INF = __int_as_float(0x7f800000);
    float ai;
    {
        // sh_x0/sh_dv pads (incl. slot 80) are zero -> RP's dval term vanishes.
        const ulonglong2* x0V = reinterpret_cast<const ulonglong2*>(sh_x0) + 11 * part;
        const ulonglong2* dvV = reinterpret_cast<const ulonglong2*>(sh_dv) + 11 * part;
        float p0 = dot44(RP, x0V);
        float p1 = dot44(RP, dvV);
        float ax0 = p0 + __shfl_xor_sync(0xffffffffu, p0, 1);
        float ad  = p1 + __shfl_xor_sync(0xffffffffu, p1, 1);
        if (rowAct) {
            float slack = fmaxf(bval - ax0, 0.0f);
            ai = (ad > 0.0f) ? (slack / (ad + 1e-12f)) : INF;
        } else {
            ai = INF;
        }
    }
    ai = warp_min(ai);
    if (lane == 0) sh_red[wid] = ai;
    __syncthreads();
    float alpha = fminf(fminf(fminf(sh_red[0], sh_red[1]), fminf(sh_red[2], sh_red[3])),
                        fminf(fminf(sh_red[4], sh_red[5]), fminf(sh_red[6], sh_red[7])));
    if (!isfinite(alpha)) alpha = 1.0f;
    alpha = fminf(fmaxf(alpha - 1e-9f, 0.0f), 1.0f);

    if (idx < N_ACT && part == 0)
        out[(size_t)prob * N_ACT + idx] = fmaxf(sh_x0[idx] + alpha * sh_dv[idx], 0.0f);
}

extern "C" void kernel_launch(void* const* d_in, const int* in_sizes, int n_in,
                              void* d_out, int out_size)
{
    const float* xhat = (const float*)d_in[0];
    const float* A    = (const float*)d_in[1];
    const float* b    = (const float*)d_in[2];
    float* out        = (float*)d_out;
    int P = in_sizes[0] / N_ACT;     // 1024 problems
    acp_kernel<<<P, 256>>>(xhat, A, b, out);
}